// round 11
// baseline (speedup 1.0000x reference)
#include <cuda_runtime.h>
#include <cuda_bf16.h>
#include <math.h>
#include <stdint.h>

#define TPB  384
#define NBLK 128

// ---- smem byte offsets ----
#define OFF_W    0         // 6 x 16384: Wh0hi,Wh0lo,Wi1hi,Wi1lo,Wh1hi,Wh1lo (frag order)
#define OFF_SCR0 98304     // D0 scratch 64*36 floats
#define OFF_SCR1 107520    // D1 partial (h1·Wi1)
#define OFF_SCR2 116736    // D1 partial (h2·Wh1)
#define OFF_WI0  125952    // 8*32 float
#define OFF_B0   126976    // 32 float
#define OFF_B1   127104    // 32 float
#define SMEM_DYN 127232

// ---------------- device scratch ----------------
// h in A-fragment order: [parity][bg*8192 + (kc*4+mc)*128 + lane*4 + reg] (b32 = bf16x2)
__device__ unsigned g_h1hi[2][32768];
__device__ unsigned g_h1lo[2][32768];
__device__ unsigned g_h2hi[2][32768];
__device__ unsigned g_h2lo[2][32768];
__device__ float    g_last[256 * 256];      // [b][u]
__device__ float    g_y[256 * 256];         // [b][j]
__device__ float    g_emb[256 * 256 * 8];   // [t][b][e]
__device__ unsigned g_barG[4][32];          // per-batch-group barriers
__device__ unsigned g_barF;

// ---------------- helpers ----------------
__device__ __forceinline__ float sigf(float x) { return 1.f / (1.f + __expf(-x)); }
__device__ __forceinline__ float tanha(float x) { return 2.f * sigf(2.f * x) - 1.f; }

__device__ __forceinline__ void hilo_pack(float v0, float v1, unsigned& hi, unsigned& lo) {
    asm("cvt.rn.bf16x2.f32 %0, %1, %2;" : "=r"(hi) : "f"(v1), "f"(v0));  // v0 low
    float l0 = v0 - __uint_as_float(hi << 16);
    float l1 = v1 - __uint_as_float(hi & 0xFFFF0000u);
    asm("cvt.rn.bf16x2.f32 %0, %1, %2;" : "=r"(lo) : "f"(l1), "f"(l0));
}

__device__ __forceinline__ void mma16816(float* acc, uint4 A, unsigned b0, unsigned b1) {
    asm("mma.sync.aligned.m16n8k16.row.col.f32.bf16.bf16.f32 "
        "{%0,%1,%2,%3}, {%4,%5,%6,%7}, {%8,%9}, {%0,%1,%2,%3};"
        : "+f"(acc[0]), "+f"(acc[1]), "+f"(acc[2]), "+f"(acc[3])
        : "r"(A.x), "r"(A.y), "r"(A.z), "r"(A.w), "r"(b0), "r"(b1));
}

__device__ __forceinline__ void bar_sync(unsigned* ctr, unsigned& gen, int n) {
    __syncthreads();
    if (threadIdx.x == 0) {
        __threadfence();
        atomicAdd(ctr, 1u);
        gen += (unsigned)n;
        unsigned v;
        do { asm volatile("ld.acquire.gpu.global.u32 %0, [%1];" : "=r"(v) : "l"(ctr)); }
        while (v < gen);
    }
    __syncthreads();
}

// ---------------- prep ----------------
__global__ void prep_kernel(const int* __restrict__ tokens,
                            const float* __restrict__ emb) {
    int idx = blockIdx.x * 256 + threadIdx.x;
    if (idx < 4) g_barG[idx][0] = 0;
    if (idx == 4) g_barF = 0;
    int b = idx >> 8, t = idx & 255;
    int tok = tokens[b * 256 + t];
    const float4* e = (const float4*)(emb + tok * 8);
    float4* d = (float4*)(g_emb + (t * 256 + b) * 8);
    d[0] = e[0]; d[1] = e[1];
}

// ---------------- persistent LSTM kernel ----------------
extern __shared__ char smem_raw[];

__global__ void __launch_bounds__(TPB, 1)
lstm_kernel(const int* __restrict__ lengths,
            const float* __restrict__ w_ih0, const float* __restrict__ w_hh0,
            const float* __restrict__ b_ih0, const float* __restrict__ b_hh0,
            const float* __restrict__ w_ih1, const float* __restrict__ w_hh1,
            const float* __restrict__ b_ih1, const float* __restrict__ b_hh1,
            const float* __restrict__ ff_w, const float* __restrict__ ff_b,
            const float* __restrict__ bn_g, const float* __restrict__ bn_b,
            float* __restrict__ out) {
    char* SB = smem_raw;
    const int tid = threadIdx.x;
    const int bid = blockIdx.x;
    const int bg = bid >> 5;      // batch group: rows bg*64 .. +63
    const int ug = bid & 31;      // unit group: units ug*8 .. +7
    const int wid = tid >> 5, lane = tid & 31;
    const int wm = wid & 3;       // m16 row block
    const int role = wid >> 2;    // 0: D0=h1·Wh0  1: D1a=h1·Wi1  2: D1b=h2·Wh1
    const int gID = lane >> 2, tig = lane & 3;
    const int bl = tid & 63, up = (tid >> 6) & 3;   // pointwise mapping (tid<256)
    const int b = bg * 64 + bl;

    float* sWi0 = (float*)(SB + OFF_WI0);
    float* sB0  = (float*)(SB + OFF_B0);
    float* sB1  = (float*)(SB + OFF_B1);
    float* scr0 = (float*)(SB + OFF_SCR0);
    float* scr1 = (float*)(SB + OFF_SCR1);
    float* scr2 = (float*)(SB + OFF_SCR2);

    // ---- pack weights into B-fragment order (bf16 hi/lo) — identical to passing R8/R9 ----
    {
        const float* srcs[3] = { w_hh0, w_ih1, w_hh1 };
#pragma unroll
        for (int m = 0; m < 3; m++) {
            const float* src = srcs[m];
            unsigned* dhi = (unsigned*)(SB + OFF_W + (2 * m) * 16384);
            unsigned* dlo = (unsigned*)(SB + OFF_W + (2 * m + 1) * 16384);
            for (int idx = tid; idx < 4096; idx += TPB) {
                int j = idx & 3, ln = (idx >> 2) & 31, wnn = (idx >> 7) & 1, kc = idx >> 8;
                int n_loc = wnn * 16 + ((j >> 1) << 3) + (ln >> 2);
                int k0 = kc * 16 + (ln & 3) * 2 + (j & 1) * 8;
                int row = (n_loc & 3) * 256 + ug * 8 + (n_loc >> 2);
                float w0 = src[row * 256 + k0], w1 = src[row * 256 + k0 + 1];
                __nv_bfloat16 h0 = __float2bfloat16(w0);
                __nv_bfloat16 h1 = __float2bfloat16(w1);
                __nv_bfloat16 l0 = __float2bfloat16(w0 - __bfloat162float(h0));
                __nv_bfloat16 l1 = __float2bfloat16(w1 - __bfloat162float(h1));
                dhi[idx] = ((unsigned)__bfloat16_as_ushort(h1) << 16) | __bfloat16_as_ushort(h0);
                dlo[idx] = ((unsigned)__bfloat16_as_ushort(l1) << 16) | __bfloat16_as_ushort(l0);
            }
        }
    }
    if (tid < 256) {
        int e = tid >> 5, c = tid & 31;
        int row = (c & 3) * 256 + ug * 8 + (c >> 2);
        sWi0[e * 32 + c] = w_ih0[row * 8 + e];
    }
    if (tid < 32) {
        int row = (tid & 3) * 256 + ug * 8 + (tid >> 2);
        sB0[tid] = b_ih0[row] + b_hh0[row];
        sB1[tid] = b_ih1[row] + b_hh1[row];
    }

    // per-thread h slot in A-frag global layout (tid<256 only)
    const int kc_u = ug >> 1;
    const int row16 = bl & 15;
    const int slot = bg * 8192 + (kc_u * 4 + (bl >> 4)) * 128 +
                     ((row16 & 7) * 4 + up) * 4 + (row16 >> 3) + 2 * (ug & 1);

    if (tid < 256) {
        g_h2hi[1][slot] = 0u;     // h2(-1) = 0
        g_h2lo[1][slot] = 0u;
    }

    const int myLen = lengths[b];
    float c1s0 = 0.f, c1s1 = 0.f, c2s0 = 0.f, c2s1 = 0.f;
    unsigned genG = 0, genF = 0;
    __syncthreads();

    // ---- prologue: h1(0) = cell(x(0), 0) ----
    if (tid < 256) {
        float xp[8];
#pragma unroll
        for (int c = 0; c < 8; c++) xp[c] = sB0[up * 8 + c];
        const float4* ep = (const float4*)(g_emb + (0 * 256 + b) * 8);
        float4 e0 = ep[0], e1 = ep[1];
        float xs[8] = { e0.x, e0.y, e0.z, e0.w, e1.x, e1.y, e1.z, e1.w };
#pragma unroll
        for (int e = 0; e < 8; e++)
#pragma unroll
            for (int c = 0; c < 8; c++) xp[c] += xs[e] * sWi0[e * 32 + up * 8 + c];
        float cc0 = sigf(xp[0]) * tanha(xp[2]);
        float h10 = sigf(xp[3]) * tanha(cc0);
        float cc1 = sigf(xp[4]) * tanha(xp[6]);
        float h11 = sigf(xp[7]) * tanha(cc1);
        c1s0 = cc0; c1s1 = cc1;
        unsigned hi, lo;
        hilo_pack(h10, h11, hi, lo);
        g_h1hi[0][slot] = hi;
        g_h1lo[0][slot] = lo;
    }
    bar_sync(&g_barG[bg][0], genG, 32);

    // A-frag base (uint4 units): bg*2048 + wm*32 + lane; kc stride = 128
    const int abase = bg * 2048 + wm * 32 + lane;
    const char* pWh = SB + OFF_W + (2 * role) * 16384 + lane * 16;
    const char* pWl = pWh + 16384;
    float* scrW = (float*)(SB + OFF_SCR0 + role * 9216);

    // ---- main loop: phase p computes h1(p+1) and h2(p) ----
    for (int p = 0; p < 256; p++) {
        const int rp = p & 1;

        // ---- role-generic MMA: D = hX · WXᵀ (3 hi/lo terms) ----
        {
            const uint4* ah = (const uint4*)(role == 2 ? g_h2hi[rp ^ 1] : g_h1hi[rp]) + abase;
            const uint4* al = (const uint4*)(role == 2 ? g_h2lo[rp ^ 1] : g_h1lo[rp]) + abase;
            float D[16];
#pragma unroll
            for (int i = 0; i < 16; i++) D[i] = 0.f;
#pragma unroll 4
            for (int kc = 0; kc < 16; kc++) {
                uint4 Ah = __ldcg(ah + kc * 128);
                uint4 Al = __ldcg(al + kc * 128);
#pragma unroll
                for (int hf = 0; hf < 2; hf++) {
                    uint4 Bh = *(const uint4*)(pWh + kc * 1024 + hf * 512);
                    uint4 Bl = *(const uint4*)(pWl + kc * 1024 + hf * 512);
                    float* d = D + hf * 8;
                    mma16816(d + 0, Ah, Bh.x, Bh.y); mma16816(d + 4, Ah, Bh.z, Bh.w);
                    mma16816(d + 0, Ah, Bl.x, Bl.y); mma16816(d + 4, Ah, Bl.z, Bl.w);
                    mma16816(d + 0, Al, Bh.x, Bh.y); mma16816(d + 4, Al, Bh.z, Bh.w);
                }
            }
            // dump (scratch was fully consumed before last bar_sync)
            int r0 = wm * 16 + gID;
#pragma unroll
            for (int hf = 0; hf < 2; hf++)
#pragma unroll
                for (int blk = 0; blk < 2; blk++) {
                    int c0 = hf * 16 + blk * 8 + tig * 2;
                    int ib = hf * 8 + blk * 4;
                    scrW[r0 * 36 + c0] = D[ib];           scrW[r0 * 36 + c0 + 1] = D[ib + 1];
                    scrW[(r0 + 8) * 36 + c0] = D[ib + 2]; scrW[(r0 + 8) * 36 + c0 + 1] = D[ib + 3];
                }
        }

        // x-part for h1(p+1) — overlaps other warps' mma tail
        float xp[8];
        if (tid < 256) {
            int tx = (p < 255) ? p + 1 : 255;
#pragma unroll
            for (int c = 0; c < 8; c++) xp[c] = sB0[up * 8 + c];
            const float4* ep = (const float4*)(g_emb + (tx * 256 + b) * 8);
            float4 e0 = ep[0], e1 = ep[1];
            float xs[8] = { e0.x, e0.y, e0.z, e0.w, e1.x, e1.y, e1.z, e1.w };
#pragma unroll
            for (int e = 0; e < 8; e++)
#pragma unroll
                for (int c = 0; c < 8; c++) xp[c] += xs[e] * sWi0[e * 32 + up * 8 + c];
        }

        __syncthreads();   // all dumps visible

        // ---- pointwise: thread owns (bl, units 2up, 2up+1) ----
        if (tid < 256) {
            const float4* q0 = (const float4*)(scr0 + bl * 36 + up * 8);
            float4 ga = q0[0], gb = q0[1];
            float cc0 = sigf(ga.y + xp[1]) * c1s0 + sigf(ga.x + xp[0]) * tanha(ga.z + xp[2]);
            float h10 = sigf(ga.w + xp[3]) * tanha(cc0);
            float cc1 = sigf(gb.y + xp[5]) * c1s1 + sigf(gb.x + xp[4]) * tanha(gb.z + xp[6]);
            float h11 = sigf(gb.w + xp[7]) * tanha(cc1);
            c1s0 = cc0; c1s1 = cc1;
            unsigned hi, lo;
            hilo_pack(h10, h11, hi, lo);
            g_h1hi[rp ^ 1][slot] = hi;
            g_h1lo[rp ^ 1][slot] = lo;

            const float4* qa = (const float4*)(scr1 + bl * 36 + up * 8);
            const float4* qb = (const float4*)(scr2 + bl * 36 + up * 8);
            float4 ha = qa[0], h2a = qb[0];
            float4 hb = qa[1], h2b = qb[1];
            float g0 = ha.x + h2a.x + sB1[up * 8 + 0];
            float g1 = ha.y + h2a.y + sB1[up * 8 + 1];
            float g2 = ha.z + h2a.z + sB1[up * 8 + 2];
            float g3 = ha.w + h2a.w + sB1[up * 8 + 3];
            float g4 = hb.x + h2b.x + sB1[up * 8 + 4];
            float g5 = hb.y + h2b.y + sB1[up * 8 + 5];
            float g6 = hb.z + h2b.z + sB1[up * 8 + 6];
            float g7 = hb.w + h2b.w + sB1[up * 8 + 7];
            float dd0 = sigf(g1) * c2s0 + sigf(g0) * tanha(g2);
            float h20 = sigf(g3) * tanha(dd0);
            float dd1 = sigf(g5) * c2s1 + sigf(g4) * tanha(g6);
            float h21 = sigf(g7) * tanha(dd1);
            c2s0 = dd0; c2s1 = dd1;
            hilo_pack(h20, h21, hi, lo);
            g_h2hi[rp][slot] = hi;
            g_h2lo[rp][slot] = lo;
            if (p == myLen - 1) {
                g_last[b * 256 + ug * 8 + 2 * up] = h20;
                g_last[b * 256 + ug * 8 + 2 * up + 1] = h21;
            }
        }
        bar_sync(&g_barG[bg][0], genG, 32);
    }

    bar_sync(&g_barF, genF, NBLK);

    // ---- y = relu(last) @ ff_w^T + ff_b : block = rows 2bid, 2bid+1 ----
    {
        float* sv = scr0;
        int br0 = 2 * bid, br1 = 2 * bid + 1;
        if (tid < 256) {
            sv[tid]       = fmaxf(g_last[br0 * 256 + tid], 0.f);
            sv[256 + tid] = fmaxf(g_last[br1 * 256 + tid], 0.f);
        }
        __syncthreads();
        if (tid < 256) {
            float a0 = ff_b[tid], a1 = a0;
            const float4* wr = (const float4*)(ff_w + tid * 256);
            const float4* h0 = (const float4*)sv;
            const float4* h1 = (const float4*)(sv + 256);
#pragma unroll 4
            for (int k4 = 0; k4 < 64; k4++) {
                float4 wv = wr[k4];
                float4 hA = h0[k4], hB = h1[k4];
                a0 += wv.x * hA.x + wv.y * hA.y + wv.z * hA.z + wv.w * hA.w;
                a1 += wv.x * hB.x + wv.y * hB.y + wv.z * hB.z + wv.w * hB.w;
            }
            g_y[br0 * 256 + tid] = a0;
            g_y[br1 * 256 + tid] = a1;
        }
    }

    bar_sync(&g_barF, genF, NBLK);

    // ---- BatchNorm over batch: block = cols 2bid, 2bid+1 ----
    {
        float* red = scr0;
        for (int r = 0; r < 2; r++) {
            int j = 2 * bid + r;
            float v = (tid < 256) ? g_y[tid * 256 + j] : 0.f;
            __syncthreads();
            if (tid < 256) red[tid] = v;
            __syncthreads();
            for (int s = 128; s > 0; s >>= 1) {
                if (tid < s) red[tid] += red[tid + s];
                __syncthreads();
            }
            float mean = red[0] * (1.f / 256.f);
            __syncthreads();
            float d = v - mean;
            if (tid < 256) red[tid] = d * d;
            __syncthreads();
            for (int s = 128; s > 0; s >>= 1) {
                if (tid < s) red[tid] += red[tid + s];
                __syncthreads();
            }
            float inv = rsqrtf(red[0] * (1.f / 256.f) + 1e-5f);
            __syncthreads();
            if (tid < 256) out[tid * 256 + j] = bn_g[j] * d * inv + bn_b[j];
        }
    }
}

// ---------------- launch ----------------
extern "C" void kernel_launch(void* const* d_in, const int* in_sizes, int n_in,
                              void* d_out, int out_size) {
    const int*   tokens    = (const int*)d_in[0];
    const int*   lengths   = (const int*)d_in[1];
    const float* embedding = (const float*)d_in[2];
    const float* w_ih0     = (const float*)d_in[3];
    const float* w_hh0     = (const float*)d_in[4];
    const float* b_ih0     = (const float*)d_in[5];
    const float* b_hh0     = (const float*)d_in[6];
    const float* w_ih1     = (const float*)d_in[7];
    const float* w_hh1     = (const float*)d_in[8];
    const float* b_ih1     = (const float*)d_in[9];
    const float* b_hh1     = (const float*)d_in[10];
    const float* ff_w      = (const float*)d_in[11];
    const float* ff_b      = (const float*)d_in[12];
    const float* bn_g      = (const float*)d_in[13];
    const float* bn_b      = (const float*)d_in[14];
    float* out = (float*)d_out;

    cudaFuncSetAttribute(lstm_kernel, cudaFuncAttributeMaxDynamicSharedMemorySize,
                         SMEM_DYN);
    prep_kernel<<<256, 256>>>(tokens, embedding);
    lstm_kernel<<<NBLK, TPB, SMEM_DYN>>>(
        lengths, w_ih0, w_hh0, b_ih0, b_hh0,
        w_ih1, w_hh1, b_ih1, b_hh1,
        ff_w, ff_b, bn_g, bn_b, out);
}

// round 12
// speedup vs baseline: 1.0633x; 1.0633x over previous
#include <cuda_runtime.h>
#include <cuda_bf16.h>
#include <math.h>
#include <stdint.h>

#define TPB  384
#define NBLK 128

// ---- smem byte offsets ----
#define OFF_W    0         // 6 x 16384: Wh0hi,Wh0lo,Wi1hi,Wi1lo,Wh1hi,Wh1lo (frag order)
#define OFF_SCR0 98304     // D0 scratch 64*36 floats
#define OFF_SCR1 107520    // D1 partial (h1·Wi1)
#define OFF_SCR2 116736    // D1 partial (h2·Wh1)
#define OFF_WI0  125952    // 8*32 float
#define OFF_B0   126976    // 32 float
#define OFF_B1   127104    // 32 float
#define SMEM_DYN 127232

// ---------------- device scratch ----------------
// h in A-fragment order: [parity][bg*8192 + (kc*4+mc)*128 + lane*4 + reg] (b32 = bf16x2)
__device__ unsigned g_h1hi[2][32768];
__device__ unsigned g_h1lo[2][32768];
__device__ unsigned g_h2hi[2][32768];
__device__ unsigned g_h2lo[2][32768];
__device__ float    g_last[256 * 256];      // [b][u]
__device__ float    g_y[256 * 256];         // [b][j]
__device__ float    g_emb[256 * 256 * 8];   // [t][b][e]
__device__ unsigned g_ctrH1[4][32];         // per-bg h1 counters (padded lines)
__device__ unsigned g_ctrH2[4][32];         // per-bg h2 counters
__device__ unsigned g_barF;

// ---------------- helpers ----------------
#define BARS(id, cnt) asm volatile("bar.sync %0, %1;" :: "r"(id), "r"(cnt) : "memory")

__device__ __forceinline__ float sigf(float x) { return 1.f / (1.f + __expf(-x)); }
__device__ __forceinline__ float tanha(float x) { return 2.f * sigf(2.f * x) - 1.f; }

__device__ __forceinline__ void hilo_pack(float v0, float v1, unsigned& hi, unsigned& lo) {
    asm("cvt.rn.bf16x2.f32 %0, %1, %2;" : "=r"(hi) : "f"(v1), "f"(v0));  // v0 low
    float l0 = v0 - __uint_as_float(hi << 16);
    float l1 = v1 - __uint_as_float(hi & 0xFFFF0000u);
    asm("cvt.rn.bf16x2.f32 %0, %1, %2;" : "=r"(lo) : "f"(l1), "f"(l0));
}

__device__ __forceinline__ void mma16816(float* acc, uint4 A, unsigned b0, unsigned b1) {
    asm("mma.sync.aligned.m16n8k16.row.col.f32.bf16.bf16.f32 "
        "{%0,%1,%2,%3}, {%4,%5,%6,%7}, {%8,%9}, {%0,%1,%2,%3};"
        : "+f"(acc[0]), "+f"(acc[1]), "+f"(acc[2]), "+f"(acc[3])
        : "r"(A.x), "r"(A.y), "r"(A.z), "r"(A.w), "r"(b0), "r"(b1));
}

__device__ __forceinline__ void spin_ctr(unsigned* ctr, unsigned target) {
    unsigned v;
    do { asm volatile("ld.acquire.gpu.global.u32 %0, [%1];" : "=r"(v) : "l"(ctr)); }
    while (v < target);
}
__device__ __forceinline__ void arrive_ctr(unsigned* ctr) {
    __threadfence();
    atomicAdd(ctr, 1u);
}

__device__ __forceinline__ void bar_syncF(unsigned& gen, int n) {
    __syncthreads();
    if (threadIdx.x == 0) {
        __threadfence();
        atomicAdd(&g_barF, 1u);
        gen += (unsigned)n;
        spin_ctr(&g_barF, gen);
    }
    __syncthreads();
}

__device__ __forceinline__ int slot_of(int bg, int ug, int bl, int up) {
    int kc_u = ug >> 1, row16 = bl & 15;
    return bg * 8192 + (kc_u * 4 + (bl >> 4)) * 128 +
           ((row16 & 7) * 4 + up) * 4 + (row16 >> 3) + 2 * (ug & 1);
}

// ---------------- prep ----------------
__global__ void prep_kernel(const int* __restrict__ tokens,
                            const float* __restrict__ emb) {
    int idx = blockIdx.x * 256 + threadIdx.x;
    if (idx < 4) { g_ctrH1[idx][0] = 0; g_ctrH2[idx][0] = 0; }
    if (idx == 4) g_barF = 0;
    int b = idx >> 8, t = idx & 255;
    int tok = tokens[b * 256 + t];
    const float4* e = (const float4*)(emb + tok * 8);
    float4* d = (float4*)(g_emb + (t * 256 + b) * 8);
    d[0] = e[0]; d[1] = e[1];
}

// ---------------- persistent LSTM kernel ----------------
extern __shared__ char smem_raw[];

__global__ void __launch_bounds__(TPB, 1)
lstm_kernel(const int* __restrict__ lengths,
            const float* __restrict__ w_ih0, const float* __restrict__ w_hh0,
            const float* __restrict__ b_ih0, const float* __restrict__ b_hh0,
            const float* __restrict__ w_ih1, const float* __restrict__ w_hh1,
            const float* __restrict__ b_ih1, const float* __restrict__ b_hh1,
            const float* __restrict__ ff_w, const float* __restrict__ ff_b,
            const float* __restrict__ bn_g, const float* __restrict__ bn_b,
            float* __restrict__ out) {
    char* SB = smem_raw;
    const int tid = threadIdx.x;
    const int bid = blockIdx.x;
    const int bg = bid >> 5;      // batch group: rows bg*64 .. +63
    const int ug = bid & 31;      // unit group: units ug*8 .. +7
    const int wid = tid >> 5, lane = tid & 31;
    const int role = wid >> 2;    // 0: D0=h1·Wh0 + h1-cell  1: D1a=h1·Wi1  2: D1b=h2·Wh1 + h2-cell
    const int wm = wid & 3;       // m16 row block within role
    const int gID = lane >> 2, tig = lane & 3;

    float* sWi0 = (float*)(SB + OFF_WI0);
    float* sB0  = (float*)(SB + OFF_B0);
    float* sB1  = (float*)(SB + OFF_B1);
    float* scr0 = (float*)(SB + OFF_SCR0);
    float* scr1 = (float*)(SB + OFF_SCR1);
    float* scr2 = (float*)(SB + OFF_SCR2);

    // ---- pack weights into B-fragment order (bf16 hi/lo) — identical to passing R8-R10 ----
    {
        const float* srcs[3] = { w_hh0, w_ih1, w_hh1 };
#pragma unroll
        for (int m = 0; m < 3; m++) {
            const float* src = srcs[m];
            unsigned* dhi = (unsigned*)(SB + OFF_W + (2 * m) * 16384);
            unsigned* dlo = (unsigned*)(SB + OFF_W + (2 * m + 1) * 16384);
            for (int idx = tid; idx < 4096; idx += TPB) {
                int j = idx & 3, ln = (idx >> 2) & 31, wnn = (idx >> 7) & 1, kc = idx >> 8;
                int n_loc = wnn * 16 + ((j >> 1) << 3) + (ln >> 2);
                int k0 = kc * 16 + (ln & 3) * 2 + (j & 1) * 8;
                int row = (n_loc & 3) * 256 + ug * 8 + (n_loc >> 2);
                float w0 = src[row * 256 + k0], w1 = src[row * 256 + k0 + 1];
                __nv_bfloat16 h0 = __float2bfloat16(w0);
                __nv_bfloat16 h1 = __float2bfloat16(w1);
                __nv_bfloat16 l0 = __float2bfloat16(w0 - __bfloat162float(h0));
                __nv_bfloat16 l1 = __float2bfloat16(w1 - __bfloat162float(h1));
                dhi[idx] = ((unsigned)__bfloat16_as_ushort(h1) << 16) | __bfloat16_as_ushort(h0);
                dlo[idx] = ((unsigned)__bfloat16_as_ushort(l1) << 16) | __bfloat16_as_ushort(l0);
            }
        }
    }
    if (tid < 256) {
        int e = tid >> 5, c = tid & 31;
        int row = (c & 3) * 256 + ug * 8 + (c >> 2);
        sWi0[e * 32 + c] = w_ih0[row * 8 + e];
    }
    if (tid < 32) {
        int row = (tid & 3) * 256 + ug * 8 + (tid >> 2);
        sB0[tid] = b_ih0[row] + b_hh0[row];
        sB1[tid] = b_ih1[row] + b_hh1[row];
    }

    // per-role pointwise mapping: thread t in role covers 2 slots (bl, up0) (bl, up0+1)
    const int rt = tid & 127;              // index within role
    const int bl = rt & 63;
    const int up0 = (rt >> 6) * 2;         // 0 or 2
    const int b = bg * 64 + bl;
    const int s0 = slot_of(bg, ug, bl, up0);
    const int s1 = slot_of(bg, ug, bl, up0 + 1);
    const int myLen = lengths[b];

    // h2(-1) = 0 in parity-1 buffer (role2 threads)
    if (role == 2) {
        g_h2hi[1][s0] = 0u; g_h2lo[1][s0] = 0u;
        g_h2hi[1][s1] = 0u; g_h2lo[1][s1] = 0u;
    }
    __syncthreads();

    // ---- prologue: h1(0) = cell(x(0), 0) (role0 threads, 2 slots each) ----
    float c1[4] = {0.f, 0.f, 0.f, 0.f};   // role0: c1 state, 2 units per slot
    float c2[4] = {0.f, 0.f, 0.f, 0.f};   // role2: c2 state
    if (role == 0) {
        const float4* ep = (const float4*)(g_emb + (0 * 256 + b) * 8);
        float4 e0 = ep[0], e1 = ep[1];
        float xs[8] = { e0.x, e0.y, e0.z, e0.w, e1.x, e1.y, e1.z, e1.w };
#pragma unroll
        for (int sl = 0; sl < 2; sl++) {
            int up = up0 + sl;
            float xp[8];
#pragma unroll
            for (int c = 0; c < 8; c++) xp[c] = sB0[up * 8 + c];
#pragma unroll
            for (int e = 0; e < 8; e++)
#pragma unroll
                for (int c = 0; c < 8; c++) xp[c] += xs[e] * sWi0[e * 32 + up * 8 + c];
            float cc0 = sigf(xp[0]) * tanha(xp[2]);
            float h10 = sigf(xp[3]) * tanha(cc0);
            float cc1 = sigf(xp[4]) * tanha(xp[6]);
            float h11 = sigf(xp[7]) * tanha(cc1);
            c1[2 * sl] = cc0; c1[2 * sl + 1] = cc1;
            unsigned hi, lo;
            hilo_pack(h10, h11, hi, lo);
            int s = sl ? s1 : s0;
            g_h1hi[0][s] = hi;
            g_h1lo[0][s] = lo;
        }
    }
    __syncthreads();
    if (tid == 0)   arrive_ctr(&g_ctrH1[bg][0]);
    if (tid == 128) arrive_ctr(&g_ctrH1[bg][0]);
    if (tid == 256) arrive_ctr(&g_ctrH2[bg][0]);

    // A-frag base (uint4 units): bg*2048 + wm*32 + lane; kc stride = 128
    const int abase = bg * 2048 + wm * 32 + lane;
    const char* pWh = SB + OFF_W + (2 * role) * 16384 + lane * 16;
    const char* pWl = pWh + 16384;
    const int r0 = wm * 16 + gID;

    unsigned genF = 0;

    // ================= role-specialized main loops =================
    if (role == 0) {
        unsigned gen = 64;
        for (int p = 0; p < 256; p++) {
            const int rp = p & 1;
            if (tid == 0) spin_ctr(&g_ctrH1[bg][0], gen);
            BARS(3, 256);                       // release role0+role1: h1(p) ready, WAR clear
            gen += 64;

            // D0 = h1·Wh0ᵀ (3 hi/lo terms)
            {
                const uint4* ah = (const uint4*)g_h1hi[rp] + abase;
                const uint4* al = (const uint4*)g_h1lo[rp] + abase;
                float D[16];
#pragma unroll
                for (int i = 0; i < 16; i++) D[i] = 0.f;
#pragma unroll 4
                for (int kc = 0; kc < 16; kc++) {
                    uint4 Ah = __ldcg(ah + kc * 128);
                    uint4 Al = __ldcg(al + kc * 128);
#pragma unroll
                    for (int hf = 0; hf < 2; hf++) {
                        uint4 Bh = *(const uint4*)(pWh + kc * 1024 + hf * 512);
                        uint4 Bl = *(const uint4*)(pWl + kc * 1024 + hf * 512);
                        float* d = D + hf * 8;
                        mma16816(d + 0, Ah, Bh.x, Bh.y); mma16816(d + 4, Ah, Bh.z, Bh.w);
                        mma16816(d + 0, Ah, Bl.x, Bl.y); mma16816(d + 4, Ah, Bl.z, Bl.w);
                        mma16816(d + 0, Al, Bh.x, Bh.y); mma16816(d + 4, Al, Bh.z, Bh.w);
                    }
                }
#pragma unroll
                for (int hf = 0; hf < 2; hf++)
#pragma unroll
                    for (int blk = 0; blk < 2; blk++) {
                        int c0 = hf * 16 + blk * 8 + tig * 2;
                        int ib = hf * 8 + blk * 4;
                        scr0[r0 * 36 + c0] = D[ib];           scr0[r0 * 36 + c0 + 1] = D[ib + 1];
                        scr0[(r0 + 8) * 36 + c0] = D[ib + 2]; scr0[(r0 + 8) * 36 + c0 + 1] = D[ib + 3];
                    }
            }
            BARS(1, 128);                       // scr0 dumped

            // x-part + pointwise h1(p+1), 2 slots
            {
                int tx = (p < 255) ? p + 1 : 255;
                const float4* ep = (const float4*)(g_emb + (tx * 256 + b) * 8);
                float4 e0 = ep[0], e1 = ep[1];
                float xs[8] = { e0.x, e0.y, e0.z, e0.w, e1.x, e1.y, e1.z, e1.w };
#pragma unroll
                for (int sl = 0; sl < 2; sl++) {
                    int up = up0 + sl;
                    float xp[8];
#pragma unroll
                    for (int c = 0; c < 8; c++) xp[c] = sB0[up * 8 + c];
#pragma unroll
                    for (int e = 0; e < 8; e++)
#pragma unroll
                        for (int c = 0; c < 8; c++) xp[c] += xs[e] * sWi0[e * 32 + up * 8 + c];
                    const float4* q0 = (const float4*)(scr0 + bl * 36 + up * 8);
                    float4 ga = q0[0], gb = q0[1];
                    float cc0 = sigf(ga.y + xp[1]) * c1[2 * sl] + sigf(ga.x + xp[0]) * tanha(ga.z + xp[2]);
                    float h10 = sigf(ga.w + xp[3]) * tanha(cc0);
                    float cc1 = sigf(gb.y + xp[5]) * c1[2 * sl + 1] + sigf(gb.x + xp[4]) * tanha(gb.z + xp[6]);
                    float h11 = sigf(gb.w + xp[7]) * tanha(cc1);
                    c1[2 * sl] = cc0; c1[2 * sl + 1] = cc1;
                    unsigned hi, lo;
                    hilo_pack(h10, h11, hi, lo);
                    int s = sl ? s1 : s0;
                    g_h1hi[rp ^ 1][s] = hi;
                    g_h1lo[rp ^ 1][s] = lo;
                }
            }
            BARS(1, 128);                       // all h1 writes issued
            if (tid == 0) arrive_ctr(&g_ctrH1[bg][0]);
        }
    } else if (role == 1) {
        unsigned gen = 64;
        for (int p = 0; p < 256; p++) {
            const int rp = p & 1;
            BARS(3, 256);                       // paired with role0's release
            gen += 64;

            // D1a = h1·Wi1ᵀ (3 terms)
            const uint4* ah = (const uint4*)g_h1hi[rp] + abase;
            const uint4* al = (const uint4*)g_h1lo[rp] + abase;
            float D[16];
#pragma unroll
            for (int i = 0; i < 16; i++) D[i] = 0.f;
#pragma unroll 4
            for (int kc = 0; kc < 16; kc++) {
                uint4 Ah = __ldcg(ah + kc * 128);
                uint4 Al = __ldcg(al + kc * 128);
#pragma unroll
                for (int hf = 0; hf < 2; hf++) {
                    uint4 Bh = *(const uint4*)(pWh + kc * 1024 + hf * 512);
                    uint4 Bl = *(const uint4*)(pWl + kc * 1024 + hf * 512);
                    float* d = D + hf * 8;
                    mma16816(d + 0, Ah, Bh.x, Bh.y); mma16816(d + 4, Ah, Bh.z, Bh.w);
                    mma16816(d + 0, Ah, Bl.x, Bl.y); mma16816(d + 4, Ah, Bl.z, Bl.w);
                    mma16816(d + 0, Al, Bh.x, Bh.y); mma16816(d + 4, Al, Bh.z, Bh.w);
                }
            }
            BARS(2, 256);                       // #1: role2's prev pointwise done (scr1 WAR)
            if (tid == 128) arrive_ctr(&g_ctrH1[bg][0]);   // reads of h1(p) complete
#pragma unroll
            for (int hf = 0; hf < 2; hf++)
#pragma unroll
                for (int blk = 0; blk < 2; blk++) {
                    int c0 = hf * 16 + blk * 8 + tig * 2;
                    int ib = hf * 8 + blk * 4;
                    scr1[r0 * 36 + c0] = D[ib];           scr1[r0 * 36 + c0 + 1] = D[ib + 1];
                    scr1[(r0 + 8) * 36 + c0] = D[ib + 2]; scr1[(r0 + 8) * 36 + c0 + 1] = D[ib + 3];
                }
            BARS(2, 256);                       // #2: scr1 ready for role2
        }
    } else {
        unsigned gen2 = 32;
        for (int p = 0; p < 256; p++) {
            const int rp = p & 1;
            if (tid == 256) spin_ctr(&g_ctrH2[bg][0], gen2);
            BARS(4, 128);                       // release role2: h2(p-1) ready
            gen2 += 32;

            // D1b = h2·Wh1ᵀ (3 terms)
            {
                const uint4* ah = (const uint4*)g_h2hi[rp ^ 1] + abase;
                const uint4* al = (const uint4*)g_h2lo[rp ^ 1] + abase;
                float D[16];
#pragma unroll
                for (int i = 0; i < 16; i++) D[i] = 0.f;
#pragma unroll 4
                for (int kc = 0; kc < 16; kc++) {
                    uint4 Ah = __ldcg(ah + kc * 128);
                    uint4 Al = __ldcg(al + kc * 128);
#pragma unroll
                    for (int hf = 0; hf < 2; hf++) {
                        uint4 Bh = *(const uint4*)(pWh + kc * 1024 + hf * 512);
                        uint4 Bl = *(const uint4*)(pWl + kc * 1024 + hf * 512);
                        float* d = D + hf * 8;
                        mma16816(d + 0, Ah, Bh.x, Bh.y); mma16816(d + 4, Ah, Bh.z, Bh.w);
                        mma16816(d + 0, Ah, Bl.x, Bl.y); mma16816(d + 4, Ah, Bl.z, Bl.w);
                        mma16816(d + 0, Al, Bh.x, Bh.y); mma16816(d + 4, Al, Bh.z, Bh.w);
                    }
                }
                BARS(2, 256);                   // #1
#pragma unroll
                for (int hf = 0; hf < 2; hf++)
#pragma unroll
                    for (int blk = 0; blk < 2; blk++) {
                        int c0 = hf * 16 + blk * 8 + tig * 2;
                        int ib = hf * 8 + blk * 4;
                        scr2[r0 * 36 + c0] = D[ib];           scr2[r0 * 36 + c0 + 1] = D[ib + 1];
                        scr2[(r0 + 8) * 36 + c0] = D[ib + 2]; scr2[(r0 + 8) * 36 + c0 + 1] = D[ib + 3];
                    }
                BARS(2, 256);                   // #2: scr1 (role1) + scr2 ready
            }

            // pointwise h2(p), 2 slots
#pragma unroll
            for (int sl = 0; sl < 2; sl++) {
                int up = up0 + sl;
                const float4* qa = (const float4*)(scr1 + bl * 36 + up * 8);
                const float4* qb = (const float4*)(scr2 + bl * 36 + up * 8);
                float4 ha = qa[0], h2a = qb[0];
                float4 hb = qa[1], h2b = qb[1];
                float g0 = ha.x + h2a.x + sB1[up * 8 + 0];
                float g1 = ha.y + h2a.y + sB1[up * 8 + 1];
                float g2 = ha.z + h2a.z + sB1[up * 8 + 2];
                float g3 = ha.w + h2a.w + sB1[up * 8 + 3];
                float g4 = hb.x + h2b.x + sB1[up * 8 + 4];
                float g5 = hb.y + h2b.y + sB1[up * 8 + 5];
                float g6 = hb.z + h2b.z + sB1[up * 8 + 6];
                float g7 = hb.w + h2b.w + sB1[up * 8 + 7];
                float dd0 = sigf(g1) * c2[2 * sl] + sigf(g0) * tanha(g2);
                float h20 = sigf(g3) * tanha(dd0);
                float dd1 = sigf(g5) * c2[2 * sl + 1] + sigf(g4) * tanha(g6);
                float h21 = sigf(g7) * tanha(dd1);
                c2[2 * sl] = dd0; c2[2 * sl + 1] = dd1;
                unsigned hi, lo;
                hilo_pack(h20, h21, hi, lo);
                int s = sl ? s1 : s0;
                g_h2hi[rp][s] = hi;
                g_h2lo[rp][s] = lo;
                if (p == myLen - 1) {
                    g_last[b * 256 + ug * 8 + 2 * up] = h20;
                    g_last[b * 256 + ug * 8 + 2 * up + 1] = h21;
                }
            }
            BARS(4, 128);                       // all role2 writes issued
            if (tid == 256) arrive_ctr(&g_ctrH2[bg][0]);
        }
    }

    // ================= tail (all threads reconverge) =================
    bar_syncF(genF, NBLK);

    // ---- y = relu(last) @ ff_w^T + ff_b : block = rows 2bid, 2bid+1 ----
    {
        float* sv = scr0;
        int br0 = 2 * bid, br1 = 2 * bid + 1;
        if (tid < 256) {
            sv[tid]       = fmaxf(g_last[br0 * 256 + tid], 0.f);
            sv[256 + tid] = fmaxf(g_last[br1 * 256 + tid], 0.f);
        }
        __syncthreads();
        if (tid < 256) {
            float a0 = ff_b[tid], a1 = a0;
            const float4* wr = (const float4*)(ff_w + tid * 256);
            const float4* h0 = (const float4*)sv;
            const float4* h1 = (const float4*)(sv + 256);
#pragma unroll 4
            for (int k4 = 0; k4 < 64; k4++) {
                float4 wv = wr[k4];
                float4 hA = h0[k4], hB = h1[k4];
                a0 += wv.x * hA.x + wv.y * hA.y + wv.z * hA.z + wv.w * hA.w;
                a1 += wv.x * hB.x + wv.y * hB.y + wv.z * hB.z + wv.w * hB.w;
            }
            g_y[br0 * 256 + tid] = a0;
            g_y[br1 * 256 + tid] = a1;
        }
    }

    bar_syncF(genF, NBLK);

    // ---- BatchNorm over batch: block = cols 2bid, 2bid+1 ----
    {
        float* red = scr0;
        for (int r = 0; r < 2; r++) {
            int j = 2 * bid + r;
            float v = (tid < 256) ? g_y[tid * 256 + j] : 0.f;
            __syncthreads();
            if (tid < 256) red[tid] = v;
            __syncthreads();
            for (int s = 128; s > 0; s >>= 1) {
                if (tid < s) red[tid] += red[tid + s];
                __syncthreads();
            }
            float mean = red[0] * (1.f / 256.f);
            __syncthreads();
            float d = v - mean;
            if (tid < 256) red[tid] = d * d;
            __syncthreads();
            for (int s = 128; s > 0; s >>= 1) {
                if (tid < s) red[tid] += red[tid + s];
                __syncthreads();
            }
            float inv = rsqrtf(red[0] * (1.f / 256.f) + 1e-5f);
            __syncthreads();
            if (tid < 256) out[tid * 256 + j] = bn_g[j] * d * inv + bn_b[j];
        }
    }
}

// ---------------- launch ----------------
extern "C" void kernel_launch(void* const* d_in, const int* in_sizes, int n_in,
                              void* d_out, int out_size) {
    const int*   tokens    = (const int*)d_in[0];
    const int*   lengths   = (const int*)d_in[1];
    const float* embedding = (const float*)d_in[2];
    const float* w_ih0     = (const float*)d_in[3];
    const float* w_hh0     = (const float*)d_in[4];
    const float* b_ih0     = (const float*)d_in[5];
    const float* b_hh0     = (const float*)d_in[6];
    const float* w_ih1     = (const float*)d_in[7];
    const float* w_hh1     = (const float*)d_in[8];
    const float* b_ih1     = (const float*)d_in[9];
    const float* b_hh1     = (const float*)d_in[10];
    const float* ff_w      = (const float*)d_in[11];
    const float* ff_b      = (const float*)d_in[12];
    const float* bn_g      = (const float*)d_in[13];
    const float* bn_b      = (const float*)d_in[14];
    float* out = (float*)d_out;

    cudaFuncSetAttribute(lstm_kernel, cudaFuncAttributeMaxDynamicSharedMemorySize,
                         SMEM_DYN);
    prep_kernel<<<256, 256>>>(tokens, embedding);
    lstm_kernel<<<NBLK, TPB, SMEM_DYN>>>(
        lengths, w_ih0, w_hh0, b_ih0, b_hh0,
        w_ih1, w_hh1, b_ih1, b_hh1,
        ff_w, ff_b, bn_g, bn_b, out);
}

// round 14
// speedup vs baseline: 1.1247x; 1.0577x over previous
#include <cuda_runtime.h>
#include <cuda_bf16.h>
#include <math.h>
#include <stdint.h>

#define TPB  384
#define NBLK 128

// ---- smem byte offsets ----
#define OFF_W    0         // 6 x 16384: Wh0hi,Wh0lo,Wi1hi,Wi1lo,Wh1hi,Wh1lo (frag order)
#define OFF_SCR0 98304     // D0 scratch 64*36 floats
#define OFF_SCR1 107520    // D1 partial (h1·Wi1)
#define OFF_SCR2 116736    // D1 partial (h2·Wh1)
#define OFF_WI0  125952    // 8*32 float
#define OFF_B0   126976    // 32 float
#define OFF_B1   127104    // 32 float
#define SMEM_DYN 127232

// ---------------- device scratch ----------------
// h in A-fragment order: [parity][bg*8192 + (kc*4+mc)*128 + lane*4 + reg] (b32 = bf16x2)
__device__ unsigned g_h1hi[2][32768];
__device__ unsigned g_h1lo[2][32768];
__device__ unsigned g_h2hi[2][32768];
__device__ unsigned g_h2lo[2][32768];
__device__ float    g_last[256 * 256];      // [b][u]
__device__ float    g_y[256 * 256];         // [b][j]
__device__ float    g_emb[256 * 256 * 8];   // [t][b][e]
__device__ unsigned g_ctrH1[4][32];         // per-bg h1 counters (padded lines)
__device__ unsigned g_ctrH2[4][32];         // per-bg h2 counters
__device__ unsigned g_barF;

// ---------------- helpers ----------------
#define BARS(id, cnt) asm volatile("bar.sync %0, %1;" :: "r"(id), "r"(cnt) : "memory")

__device__ __forceinline__ float sigf(float x) { return 1.f / (1.f + __expf(-x)); }
__device__ __forceinline__ float tanha(float x) { return 2.f * sigf(2.f * x) - 1.f; }

__device__ __forceinline__ void hilo_pack(float v0, float v1, unsigned& hi, unsigned& lo) {
    asm("cvt.rn.bf16x2.f32 %0, %1, %2;" : "=r"(hi) : "f"(v1), "f"(v0));  // v0 low
    float l0 = v0 - __uint_as_float(hi << 16);
    float l1 = v1 - __uint_as_float(hi & 0xFFFF0000u);
    asm("cvt.rn.bf16x2.f32 %0, %1, %2;" : "=r"(lo) : "f"(l1), "f"(l0));
}

__device__ __forceinline__ void mma16816(float* acc, uint4 A, unsigned b0, unsigned b1) {
    asm("mma.sync.aligned.m16n8k16.row.col.f32.bf16.bf16.f32 "
        "{%0,%1,%2,%3}, {%4,%5,%6,%7}, {%8,%9}, {%0,%1,%2,%3};"
        : "+f"(acc[0]), "+f"(acc[1]), "+f"(acc[2]), "+f"(acc[3])
        : "r"(A.x), "r"(A.y), "r"(A.z), "r"(A.w), "r"(b0), "r"(b1));
}

__device__ __forceinline__ void spin_ctr(unsigned* ctr, unsigned target) {
    unsigned v;
    do { asm volatile("ld.acquire.gpu.global.u32 %0, [%1];" : "=r"(v) : "l"(ctr)); }
    while (v < target);
}
__device__ __forceinline__ void arrive_ctr(unsigned* ctr) {
    __threadfence();
    atomicAdd(ctr, 1u);
}

__device__ __forceinline__ void bar_syncF(unsigned& gen, int n) {
    __syncthreads();
    if (threadIdx.x == 0) {
        __threadfence();
        atomicAdd(&g_barF, 1u);
        gen += (unsigned)n;
        spin_ctr(&g_barF, gen);
    }
    __syncthreads();
}

__device__ __forceinline__ int slot_of(int bg, int ug, int bl, int up) {
    int kc_u = ug >> 1, row16 = bl & 15;
    return bg * 8192 + (kc_u * 4 + (bl >> 4)) * 128 +
           ((row16 & 7) * 4 + up) * 4 + (row16 >> 3) + 2 * (ug & 1);
}

// ---------------- prep ----------------
__global__ void prep_kernel(const int* __restrict__ tokens,
                            const float* __restrict__ emb) {
    int idx = blockIdx.x * 256 + threadIdx.x;
    if (idx < 4) { g_ctrH1[idx][0] = 0; g_ctrH2[idx][0] = 0; }
    if (idx == 4) g_barF = 0;
    int b = idx >> 8, t = idx & 255;
    int tok = tokens[b * 256 + t];
    const float4* e = (const float4*)(emb + tok * 8);
    float4* d = (float4*)(g_emb + (t * 256 + b) * 8);
    d[0] = e[0]; d[1] = e[1];
}

// ---------------- persistent LSTM kernel ----------------
extern __shared__ char smem_raw[];

__global__ void __launch_bounds__(TPB, 1)
lstm_kernel(const int* __restrict__ lengths,
            const float* __restrict__ w_ih0, const float* __restrict__ w_hh0,
            const float* __restrict__ b_ih0, const float* __restrict__ b_hh0,
            const float* __restrict__ w_ih1, const float* __restrict__ w_hh1,
            const float* __restrict__ b_ih1, const float* __restrict__ b_hh1,
            const float* __restrict__ ff_w, const float* __restrict__ ff_b,
            const float* __restrict__ bn_g, const float* __restrict__ bn_b,
            float* __restrict__ out) {
    char* SB = smem_raw;
    const int tid = threadIdx.x;
    const int bid = blockIdx.x;
    const int bg = bid >> 5;      // batch group: rows bg*64 .. +63
    const int ug = bid & 31;      // unit group: units ug*8 .. +7
    const int wid = tid >> 5, lane = tid & 31;
    const int role = wid >> 2;    // 0: D0+h1-cell  1: D1a  2: D1b+h2-cell
    const int wm = wid & 3;       // m16 row block within role
    const int gID = lane >> 2, tig = lane & 3;

    float* sWi0 = (float*)(SB + OFF_WI0);
    float* sB0  = (float*)(SB + OFF_B0);
    float* sB1  = (float*)(SB + OFF_B1);
    float* scr0 = (float*)(SB + OFF_SCR0);
    float* scr1 = (float*)(SB + OFF_SCR1);
    float* scr2 = (float*)(SB + OFF_SCR2);

    // ---- pack weights into B-fragment order (bf16 hi/lo) — identical to R8-R11 ----
    {
        const float* srcs[3] = { w_hh0, w_ih1, w_hh1 };
#pragma unroll
        for (int m = 0; m < 3; m++) {
            const float* src = srcs[m];
            unsigned* dhi = (unsigned*)(SB + OFF_W + (2 * m) * 16384);
            unsigned* dlo = (unsigned*)(SB + OFF_W + (2 * m + 1) * 16384);
            for (int idx = tid; idx < 4096; idx += TPB) {
                int j = idx & 3, ln = (idx >> 2) & 31, wnn = (idx >> 7) & 1, kc = idx >> 8;
                int n_loc = wnn * 16 + ((j >> 1) << 3) + (ln >> 2);
                int k0 = kc * 16 + (ln & 3) * 2 + (j & 1) * 8;
                int row = (n_loc & 3) * 256 + ug * 8 + (n_loc >> 2);
                float w0 = src[row * 256 + k0], w1 = src[row * 256 + k0 + 1];
                __nv_bfloat16 h0 = __float2bfloat16(w0);
                __nv_bfloat16 h1 = __float2bfloat16(w1);
                __nv_bfloat16 l0 = __float2bfloat16(w0 - __bfloat162float(h0));
                __nv_bfloat16 l1 = __float2bfloat16(w1 - __bfloat162float(h1));
                dhi[idx] = ((unsigned)__bfloat16_as_ushort(h1) << 16) | __bfloat16_as_ushort(h0);
                dlo[idx] = ((unsigned)__bfloat16_as_ushort(l1) << 16) | __bfloat16_as_ushort(l0);
            }
        }
    }
    if (tid < 256) {
        int e = tid >> 5, c = tid & 31;
        int row = (c & 3) * 256 + ug * 8 + (c >> 2);
        sWi0[e * 32 + c] = w_ih0[row * 8 + e];
    }
    if (tid < 32) {
        int row = (tid & 3) * 256 + ug * 8 + (tid >> 2);
        sB0[tid] = b_ih0[row] + b_hh0[row];
        sB1[tid] = b_ih1[row] + b_hh1[row];
    }

    // per-role pointwise mapping: thread covers slots (bl, up0), (bl, up0+1)
    const int rt = tid & 127;
    const int bl = rt & 63;
    const int up0 = (rt >> 6) * 2;
    const int b = bg * 64 + bl;
    const int s0 = slot_of(bg, ug, bl, up0);
    const int s1 = slot_of(bg, ug, bl, up0 + 1);
    const int myLen = lengths[b];

    if (role == 2) {   // h2(-1) = 0 in parity-1 buffer
        g_h2hi[1][s0] = 0u; g_h2lo[1][s0] = 0u;
        g_h2hi[1][s1] = 0u; g_h2lo[1][s1] = 0u;
    }
    __syncthreads();

    // ---- prologue: h1(0) = cell(x(0), 0) (role0) ----
    float c1[4] = {0.f, 0.f, 0.f, 0.f};
    float c2[4] = {0.f, 0.f, 0.f, 0.f};
    if (role == 0) {
        const float4* ep = (const float4*)(g_emb + (0 * 256 + b) * 8);
        float4 e0 = ep[0], e1 = ep[1];
        float xs[8] = { e0.x, e0.y, e0.z, e0.w, e1.x, e1.y, e1.z, e1.w };
#pragma unroll
        for (int sl = 0; sl < 2; sl++) {
            int up = up0 + sl;
            float xp[8];
#pragma unroll
            for (int c = 0; c < 8; c++) xp[c] = sB0[up * 8 + c];
#pragma unroll
            for (int e = 0; e < 8; e++)
#pragma unroll
                for (int c = 0; c < 8; c++) xp[c] += xs[e] * sWi0[e * 32 + up * 8 + c];
            float cc0 = sigf(xp[0]) * tanha(xp[2]);
            float h10 = sigf(xp[3]) * tanha(cc0);
            float cc1 = sigf(xp[4]) * tanha(xp[6]);
            float h11 = sigf(xp[7]) * tanha(cc1);
            c1[2 * sl] = cc0; c1[2 * sl + 1] = cc1;
            unsigned hi, lo;
            hilo_pack(h10, h11, hi, lo);
            int s = sl ? s1 : s0;
            g_h1hi[0][s] = hi;
            g_h1lo[0][s] = lo;
        }
    }
    __syncthreads();
    if (tid == 0)   arrive_ctr(&g_ctrH1[bg][0]);
    if (tid == 128) arrive_ctr(&g_ctrH1[bg][0]);
    if (tid == 256) arrive_ctr(&g_ctrH2[bg][0]);

    // A-frag base (uint4 units): bg*2048 + wm*32 + lane; kc stride = 128
    const int abase = bg * 2048 + wm * 32 + lane;
    const char* pWh = SB + OFF_W + (2 * role) * 16384 + lane * 16;
    const char* pWl = pWh + 16384;
    const int r0 = wm * 16 + gID;

    unsigned genF = 0;

    // ================= role-specialized main loops =================
    // Named barriers (all matched-count bar.sync, no bar.arrive):
    //   1: role0-internal (128)    3: role0 release (128)
    //   5: role1 release (128)     9: role1-internal (128)
    //   4: role2 release (128)     2: role1+role2 scr1/scr2 handshake (256), 2x per step
    if (role == 0) {
        unsigned gen = 64;
        for (int p = 0; p < 256; p++) {
            const int rp = p & 1;

            // x-part for h1(p+1) — precomputed OFF the critical path
            float xpA[8], xpB[8];
            {
                int tx = (p < 255) ? p + 1 : 255;
                const float4* ep = (const float4*)(g_emb + (tx * 256 + b) * 8);
                float4 e0 = ep[0], e1 = ep[1];
                float xs[8] = { e0.x, e0.y, e0.z, e0.w, e1.x, e1.y, e1.z, e1.w };
#pragma unroll
                for (int c = 0; c < 8; c++) {
                    xpA[c] = sB0[up0 * 8 + c];
                    xpB[c] = sB0[(up0 + 1) * 8 + c];
                }
#pragma unroll
                for (int e = 0; e < 8; e++)
#pragma unroll
                    for (int c = 0; c < 8; c++) {
                        xpA[c] += xs[e] * sWi0[e * 32 + up0 * 8 + c];
                        xpB[c] += xs[e] * sWi0[e * 32 + (up0 + 1) * 8 + c];
                    }
            }

            if (tid == 0) spin_ctr(&g_ctrH1[bg][0], gen);
            gen += 64;
            BARS(3, 128);                       // role0 release: h1(p) ready

            // D0 = h1·Wh0ᵀ (3 hi/lo terms)
            {
                const uint4* ah = (const uint4*)g_h1hi[rp] + abase;
                const uint4* al = (const uint4*)g_h1lo[rp] + abase;
                float D[16];
#pragma unroll
                for (int i = 0; i < 16; i++) D[i] = 0.f;
#pragma unroll 4
                for (int kc = 0; kc < 16; kc++) {
                    uint4 Ah = __ldcg(ah + kc * 128);
                    uint4 Al = __ldcg(al + kc * 128);
#pragma unroll
                    for (int hf = 0; hf < 2; hf++) {
                        uint4 Bh = *(const uint4*)(pWh + kc * 1024 + hf * 512);
                        uint4 Bl = *(const uint4*)(pWl + kc * 1024 + hf * 512);
                        float* d = D + hf * 8;
                        mma16816(d + 0, Ah, Bh.x, Bh.y); mma16816(d + 4, Ah, Bh.z, Bh.w);
                        mma16816(d + 0, Ah, Bl.x, Bl.y); mma16816(d + 4, Ah, Bl.z, Bl.w);
                        mma16816(d + 0, Al, Bh.x, Bh.y); mma16816(d + 4, Al, Bh.z, Bh.w);
                    }
                }
#pragma unroll
                for (int hf = 0; hf < 2; hf++)
#pragma unroll
                    for (int blk = 0; blk < 2; blk++) {
                        int c0 = hf * 16 + blk * 8 + tig * 2;
                        int ib = hf * 8 + blk * 4;
                        scr0[r0 * 36 + c0] = D[ib];           scr0[r0 * 36 + c0 + 1] = D[ib + 1];
                        scr0[(r0 + 8) * 36 + c0] = D[ib + 2]; scr0[(r0 + 8) * 36 + c0 + 1] = D[ib + 3];
                    }
            }
            BARS(1, 128);                       // scr0 dumped

            // pointwise h1(p+1), 2 slots, precomputed x-parts
#pragma unroll
            for (int sl = 0; sl < 2; sl++) {
                int up = up0 + sl;
                float* xp = sl ? xpB : xpA;
                const float4* q0 = (const float4*)(scr0 + bl * 36 + up * 8);
                float4 ga = q0[0], gb = q0[1];
                float cc0 = sigf(ga.y + xp[1]) * c1[2 * sl] + sigf(ga.x + xp[0]) * tanha(ga.z + xp[2]);
                float h10 = sigf(ga.w + xp[3]) * tanha(cc0);
                float cc1 = sigf(gb.y + xp[5]) * c1[2 * sl + 1] + sigf(gb.x + xp[4]) * tanha(gb.z + xp[6]);
                float h11 = sigf(gb.w + xp[7]) * tanha(cc1);
                c1[2 * sl] = cc0; c1[2 * sl + 1] = cc1;
                unsigned hi, lo;
                hilo_pack(h10, h11, hi, lo);
                int s = sl ? s1 : s0;
                g_h1hi[rp ^ 1][s] = hi;
                g_h1lo[rp ^ 1][s] = lo;
            }
            BARS(1, 128);                       // all h1 writes issued
            if (tid == 0) arrive_ctr(&g_ctrH1[bg][0]);
        }
    } else if (role == 1) {
        unsigned gen = 64;
        for (int p = 0; p < 256; p++) {
            const int rp = p & 1;
            if (tid == 128) spin_ctr(&g_ctrH1[bg][0], gen);
            gen += 64;
            BARS(5, 128);                       // role1 release: h1(p) ready

            // D1a = h1·Wi1ᵀ (3 terms)
            const uint4* ah = (const uint4*)g_h1hi[rp] + abase;
            const uint4* al = (const uint4*)g_h1lo[rp] + abase;
            float D[16];
#pragma unroll
            for (int i = 0; i < 16; i++) D[i] = 0.f;
#pragma unroll 4
            for (int kc = 0; kc < 16; kc++) {
                uint4 Ah = __ldcg(ah + kc * 128);
                uint4 Al = __ldcg(al + kc * 128);
#pragma unroll
                for (int hf = 0; hf < 2; hf++) {
                    uint4 Bh = *(const uint4*)(pWh + kc * 1024 + hf * 512);
                    uint4 Bl = *(const uint4*)(pWl + kc * 1024 + hf * 512);
                    float* d = D + hf * 8;
                    mma16816(d + 0, Ah, Bh.x, Bh.y); mma16816(d + 4, Ah, Bh.z, Bh.w);
                    mma16816(d + 0, Ah, Bl.x, Bl.y); mma16816(d + 4, Ah, Bl.z, Bl.w);
                    mma16816(d + 0, Al, Bh.x, Bh.y); mma16816(d + 4, Al, Bh.z, Bh.w);
                }
            }
            BARS(9, 128);                       // all role1 h1 reads complete
            if (tid == 128) arrive_ctr(&g_ctrH1[bg][0]);   // release h1 WAR immediately

            BARS(2, 256);                       // #1: role2's prev pointwise done (scr1 WAR)
#pragma unroll
            for (int hf = 0; hf < 2; hf++)
#pragma unroll
                for (int blk = 0; blk < 2; blk++) {
                    int c0 = hf * 16 + blk * 8 + tig * 2;
                    int ib = hf * 8 + blk * 4;
                    scr1[r0 * 36 + c0] = D[ib];           scr1[r0 * 36 + c0 + 1] = D[ib + 1];
                    scr1[(r0 + 8) * 36 + c0] = D[ib + 2]; scr1[(r0 + 8) * 36 + c0 + 1] = D[ib + 3];
                }
            BARS(2, 256);                       // #2: scr1 ready for role2
        }
    } else {
        unsigned gen2 = 32;
        for (int p = 0; p < 256; p++) {
            const int rp = p & 1;
            if (tid == 256) spin_ctr(&g_ctrH2[bg][0], gen2);
            gen2 += 32;
            BARS(4, 128);                       // role2 release: h2(p-1) ready

            // D1b = h2·Wh1ᵀ (3 terms)
            {
                const uint4* ah = (const uint4*)g_h2hi[rp ^ 1] + abase;
                const uint4* al = (const uint4*)g_h2lo[rp ^ 1] + abase;
                float D[16];
#pragma unroll
                for (int i = 0; i < 16; i++) D[i] = 0.f;
#pragma unroll 4
                for (int kc = 0; kc < 16; kc++) {
                    uint4 Ah = __ldcg(ah + kc * 128);
                    uint4 Al = __ldcg(al + kc * 128);
#pragma unroll
                    for (int hf = 0; hf < 2; hf++) {
                        uint4 Bh = *(const uint4*)(pWh + kc * 1024 + hf * 512);
                        uint4 Bl = *(const uint4*)(pWl + kc * 1024 + hf * 512);
                        float* d = D + hf * 8;
                        mma16816(d + 0, Ah, Bh.x, Bh.y); mma16816(d + 4, Ah, Bh.z, Bh.w);
                        mma16816(d + 0, Ah, Bl.x, Bl.y); mma16816(d + 4, Ah, Bl.z, Bl.w);
                        mma16816(d + 0, Al, Bh.x, Bh.y); mma16816(d + 4, Al, Bh.z, Bh.w);
                    }
                }
                BARS(2, 256);                   // #1: pair with role1 (scr WAR clear)
#pragma unroll
                for (int hf = 0; hf < 2; hf++)
#pragma unroll
                    for (int blk = 0; blk < 2; blk++) {
                        int c0 = hf * 16 + blk * 8 + tig * 2;
                        int ib = hf * 8 + blk * 4;
                        scr2[r0 * 36 + c0] = D[ib];           scr2[r0 * 36 + c0 + 1] = D[ib + 1];
                        scr2[(r0 + 8) * 36 + c0] = D[ib + 2]; scr2[(r0 + 8) * 36 + c0 + 1] = D[ib + 3];
                    }
                BARS(2, 256);                   // #2: scr1 + scr2 ready
            }

            // pointwise h2(p)
#pragma unroll
            for (int sl = 0; sl < 2; sl++) {
                int up = up0 + sl;
                const float4* qa = (const float4*)(scr1 + bl * 36 + up * 8);
                const float4* qb = (const float4*)(scr2 + bl * 36 + up * 8);
                float4 ha = qa[0], h2a = qb[0];
                float4 hb = qa[1], h2b = qb[1];
                float g0 = ha.x + h2a.x + sB1[up * 8 + 0];
                float g1 = ha.y + h2a.y + sB1[up * 8 + 1];
                float g2 = ha.z + h2a.z + sB1[up * 8 + 2];
                float g3 = ha.w + h2a.w + sB1[up * 8 + 3];
                float g4 = hb.x + h2b.x + sB1[up * 8 + 4];
                float g5 = hb.y + h2b.y + sB1[up * 8 + 5];
                float g6 = hb.z + h2b.z + sB1[up * 8 + 6];
                float g7 = hb.w + h2b.w + sB1[up * 8 + 7];
                float dd0 = sigf(g1) * c2[2 * sl] + sigf(g0) * tanha(g2);
                float h20 = sigf(g3) * tanha(dd0);
                float dd1 = sigf(g5) * c2[2 * sl + 1] + sigf(g4) * tanha(g6);
                float h21 = sigf(g7) * tanha(dd1);
                c2[2 * sl] = dd0; c2[2 * sl + 1] = dd1;
                unsigned hi, lo;
                hilo_pack(h20, h21, hi, lo);
                int s = sl ? s1 : s0;
                g_h2hi[rp][s] = hi;
                g_h2lo[rp][s] = lo;
                if (p == myLen - 1) {
                    g_last[b * 256 + ug * 8 + 2 * up] = h20;
                    g_last[b * 256 + ug * 8 + 2 * up + 1] = h21;
                }
            }
            BARS(4, 128);                       // all role2 writes issued
            if (tid == 256) arrive_ctr(&g_ctrH2[bg][0]);
        }
    }

    // ================= tail (all threads reconverge) =================
    bar_syncF(genF, NBLK);

    // ---- y = relu(last) @ ff_w^T + ff_b : block = rows 2bid, 2bid+1 ----
    {
        float* sv = scr0;
        int br0 = 2 * bid, br1 = 2 * bid + 1;
        if (tid < 256) {
            sv[tid]       = fmaxf(g_last[br0 * 256 + tid], 0.f);
            sv[256 + tid] = fmaxf(g_last[br1 * 256 + tid], 0.f);
        }
        __syncthreads();
        if (tid < 256) {
            float a0 = ff_b[tid], a1 = a0;
            const float4* wr = (const float4*)(ff_w + tid * 256);
            const float4* h0 = (const float4*)sv;
            const float4* h1 = (const float4*)(sv + 256);
#pragma unroll 4
            for (int k4 = 0; k4 < 64; k4++) {
                float4 wv = wr[k4];
                float4 hA = h0[k4], hB = h1[k4];
                a0 += wv.x * hA.x + wv.y * hA.y + wv.z * hA.z + wv.w * hA.w;
                a1 += wv.x * hB.x + wv.y * hB.y + wv.z * hB.z + wv.w * hB.w;
            }
            g_y[br0 * 256 + tid] = a0;
            g_y[br1 * 256 + tid] = a1;
        }
    }

    bar_syncF(genF, NBLK);

    // ---- BatchNorm over batch: block = cols 2bid, 2bid+1 ----
    {
        float* red = scr0;
        for (int r = 0; r < 2; r++) {
            int j = 2 * bid + r;
            float v = (tid < 256) ? g_y[tid * 256 + j] : 0.f;
            __syncthreads();
            if (tid < 256) red[tid] = v;
            __syncthreads();
            for (int s = 128; s > 0; s >>= 1) {
                if (tid < s) red[tid] += red[tid + s];
                __syncthreads();
            }
            float mean = red[0] * (1.f / 256.f);
            __syncthreads();
            float d = v - mean;
            if (tid < 256) red[tid] = d * d;
            __syncthreads();
            for (int s = 128; s > 0; s >>= 1) {
                if (tid < s) red[tid] += red[tid + s];
                __syncthreads();
            }
            float inv = rsqrtf(red[0] * (1.f / 256.f) + 1e-5f);
            __syncthreads();
            if (tid < 256) out[tid * 256 + j] = bn_g[j] * d * inv + bn_b[j];
        }
    }
}

// ---------------- launch ----------------
extern "C" void kernel_launch(void* const* d_in, const int* in_sizes, int n_in,
                              void* d_out, int out_size) {
    const int*   tokens    = (const int*)d_in[0];
    const int*   lengths   = (const int*)d_in[1];
    const float* embedding = (const float*)d_in[2];
    const float* w_ih0     = (const float*)d_in[3];
    const float* w_hh0     = (const float*)d_in[4];
    const float* b_ih0     = (const float*)d_in[5];
    const float* b_hh0     = (const float*)d_in[6];
    const float* w_ih1     = (const float*)d_in[7];
    const float* w_hh1     = (const float*)d_in[8];
    const float* b_ih1     = (const float*)d_in[9];
    const float* b_hh1     = (const float*)d_in[10];
    const float* ff_w      = (const float*)d_in[11];
    const float* ff_b      = (const float*)d_in[12];
    const float* bn_g      = (const float*)d_in[13];
    const float* bn_b      = (const float*)d_in[14];
    float* out = (float*)d_out;

    cudaFuncSetAttribute(lstm_kernel, cudaFuncAttributeMaxDynamicSharedMemorySize,
                         SMEM_DYN);
    prep_kernel<<<256, 256>>>(tokens, embedding);
    lstm_kernel<<<NBLK, TPB, SMEM_DYN>>>(
        lengths, w_ih0, w_hh0, b_ih0, b_hh0,
        w_ih1, w_hh1, b_ih1, b_hh1,
        ff_w, ff_b, bn_g, bn_b, out);
}